// round 16
// baseline (speedup 1.0000x reference)
#include <cuda_runtime.h>
#include <cuda_fp16.h>
#include <cstdint>

// ============================================================================
// PackedBitLinear: out = x @ W^T * scale   (abs-max row scaling cancels).
// tcgen05 rejected by harness PTX target (sm_103 w/o 'a') -> HMMA mma.sync.
// R16 = R15 resubmitted (R15 bench was an infra failure, no kernel signal).
// BK=128/2-stage ring (half the stage boundaries), cross-kk fragment
// double-buffering (LDSM latency fully hidden), 1 producer warp (288 thr ->
// 227-reg cap), prep kernels fused.
//   kernel 1: prep: x fp32->fp16 (g_XH) + packed 2-bit->fp16 (g_WH)
//   kernel 2: warp-specialized GEMM 128x256x128, 2-stage mbarrier ring
// ============================================================================

#define TOKENS 8192
#define NF 4096
#define KF 4096

#define BM 128
#define BN 256
#define BK 128                    // halves of K per stage (256B/row)
#define KT (KF / BK)              // 32
#define STAGES 2
#define LDSH 136                  // row stride in halves
#define ROWB (LDSH * 2)           // 272 B
#define A_STG_B (BM * ROWB)       // 34816
#define B_STG_B (BN * ROWB)       // 69632
#define STG_B (A_STG_B + B_STG_B) // 104448
#define SM_TILE 1024
#define SMEM_TOTAL (SM_TILE + STAGES * STG_B)   // 209920

#define NTHREADS 288              // 8 consumer warps + 1 producer warp

#define X_BLOCKS 16384            // prep: 16384*256*8 = 33.5M x-elems
#define W_BLOCKS 4096             // prep: 4096*256 = 1M packed ints

static __device__ __half g_XH[(size_t)TOKENS * KF];   // 64 MB fp16 activations
static __device__ __half g_WH[(size_t)NF * KF];       // 32 MB fp16 weights

// ---------------------------------------------------------------------------
__device__ __forceinline__ uint32_t smem_u32(const void* p) {
    uint32_t a;
    asm("{ .reg .u64 t; cvta.to.shared.u64 t, %1; cvt.u32.u64 %0, t; }" : "=r"(a) : "l"(p));
    return a;
}
#define MBAR_INIT(a, n) \
    asm volatile("mbarrier.init.shared.b64 [%0], %1;" :: "r"(a), "r"((uint32_t)(n)) : "memory")
#define MBAR_ARRIVE(a) \
    asm volatile("mbarrier.arrive.release.cta.shared::cta.b64 _, [%0];" :: "r"(a) : "memory")

__device__ __forceinline__ void mbar_wait(uint32_t addr, uint32_t parity) {
    uint32_t done;
    asm volatile(
        "{ .reg .pred p; mbarrier.try_wait.parity.acquire.cta.shared::cta.b64 p, [%1], %2;"
        " selp.b32 %0,1,0,p; }" : "=r"(done) : "r"(addr), "r"(parity) : "memory");
    if (!done) {
        asm volatile(
            "{ .reg .pred P1;\n"
            "W_%=: mbarrier.try_wait.parity.acquire.cta.shared::cta.b64 P1, [%0], %1, 0x989680;\n"
            "@P1 bra.uni D_%=; bra.uni W_%=; D_%=: }\n"
            :: "r"(addr), "r"(parity) : "memory");
    }
}
#define CPA16(dst, src) \
    asm volatile("cp.async.cg.shared.global [%0], [%1], 16;\n" :: "r"(dst), "l"(src))
#define CPA_MBAR(b) \
    asm volatile("cp.async.mbarrier.arrive.noinc.shared::cta.b64 [%0];" :: "r"(b) : "memory")

__device__ __forceinline__ void ldsm_x4(uint32_t (&r)[4], uint32_t addr) {
    asm volatile("ldmatrix.sync.aligned.m8n8.x4.shared.b16 {%0,%1,%2,%3}, [%4];\n"
                 : "=r"(r[0]), "=r"(r[1]), "=r"(r[2]), "=r"(r[3]) : "r"(addr));
}
__device__ __forceinline__ void mma16816(float (&c)[4], const uint32_t (&a)[4],
                                         uint32_t b0, uint32_t b1) {
    asm volatile(
        "mma.sync.aligned.m16n8k16.row.col.f32.f16.f16.f32 "
        "{%0,%1,%2,%3},{%4,%5,%6,%7},{%8,%9},{%0,%1,%2,%3};\n"
        : "+f"(c[0]), "+f"(c[1]), "+f"(c[2]), "+f"(c[3])
        : "r"(a[0]), "r"(a[1]), "r"(a[2]), "r"(a[3]), "r"(b0), "r"(b1));
}

// ---------------------------------------------------------------------------
// Kernel 1: fused prep. Blocks [0, X_BLOCKS): x fp32 -> fp16.
//           Blocks [X_BLOCKS, X_BLOCKS+W_BLOCKS): packed 2-bit -> fp16.
// half bits 0x6400|v == 1024+v exactly; hsub2 with 1025 -> v-1, exact.
// ---------------------------------------------------------------------------
__global__ void __launch_bounds__(256) prep_kernel(const float* __restrict__ x,
                                                   const int* __restrict__ pw) {
    if (blockIdx.x < X_BLOCKS) {
        size_t i = (size_t)blockIdx.x * 256 + threadIdx.x;     // 8-elem chunk
        const float4* p = reinterpret_cast<const float4*>(x) + 2 * i;
        float4 a = p[0], b = p[1];
        __half2 h0 = __floats2half2_rn(a.x, a.y), h1 = __floats2half2_rn(a.z, a.w);
        __half2 h2 = __floats2half2_rn(b.x, b.y), h3 = __floats2half2_rn(b.z, b.w);
        uint4 u;
        u.x = *reinterpret_cast<uint32_t*>(&h0); u.y = *reinterpret_cast<uint32_t*>(&h1);
        u.z = *reinterpret_cast<uint32_t*>(&h2); u.w = *reinterpret_cast<uint32_t*>(&h3);
        reinterpret_cast<uint4*>(g_XH)[i] = u;
    } else {
        size_t i = (size_t)(blockIdx.x - X_BLOCKS) * 256 + threadIdx.x;  // one int32
        int v = pw[i];
        const uint32_t c1025 = 0x64016401u;
        uint32_t r[8];
#pragma unroll
        for (int j = 0; j < 8; j++) {
            uint32_t lo = ((uint32_t)v >> (4 * j)) & 3u;
            uint32_t hi = ((uint32_t)v >> (4 * j + 2)) & 3u;
            uint32_t pk = 0x64006400u | lo | (hi << 16);
            __half2 h = __hsub2(*reinterpret_cast<__half2*>(&pk),
                                *reinterpret_cast<const __half2*>(&c1025));
            r[j] = *reinterpret_cast<uint32_t*>(&h);
        }
        uint4* dst = reinterpret_cast<uint4*>(g_WH + i * 16);
        dst[0] = make_uint4(r[0], r[1], r[2], r[3]);
        dst[1] = make_uint4(r[4], r[5], r[6], r[7]);
    }
}

// ---------------------------------------------------------------------------
// Kernel 2: warp-specialized GEMM
// ---------------------------------------------------------------------------
__global__ void __launch_bounds__(NTHREADS, 1) gemm_kernel(float* __restrict__ out,
                                                           const float* __restrict__ scale) {
    extern __shared__ char smem[];
    const uint32_t sb = smem_u32(smem);
    const int tid = threadIdx.x, wid = tid >> 5, lane = tid & 31;
    const int bn0 = blockIdx.x * BN, bm0 = blockIdx.y * BM;

    if (tid == 0) {
#pragma unroll
        for (int s = 0; s < STAGES; s++) {
            MBAR_INIT(sb + s * 8, 32);         // full: 32 producer cp-arrivals
            MBAR_INIT(sb + 32 + s * 8, 8);     // empty: 8 consumer warps
        }
    }
    __syncthreads();

    if (wid == 8) {
        // ========== producer (1 warp, pure cp.async) ==========
        const int pt = lane;                    // 0..31
        const __half* gA = g_XH + (size_t)bm0 * KF;
        const __half* gB = g_WH + (size_t)bn0 * KF;
        int slot = 0; uint32_t ph = 1;          // empty barriers start "ready"
        for (int kt = 0; kt < KT; kt++) {
            mbar_wait(sb + 32 + slot * 8, ph);
            const uint32_t sA = sb + SM_TILE + slot * STG_B;
            const uint32_t sB = sA + A_STG_B;
            const size_t k0 = (size_t)kt * BK;
#pragma unroll 16
            for (int i = 0; i < 64; i++) {      // A: 2048 16B chunks / 32 thr
                int c = pt + i * 32;
                int row = c >> 4, ci = c & 15;
                CPA16(sA + (uint32_t)row * ROWB + ci * 16,
                      gA + (size_t)row * KF + k0 + ci * 8);
            }
#pragma unroll 16
            for (int i = 0; i < 128; i++) {     // B: 4096 16B chunks / 32 thr
                int c = pt + i * 32;
                int row = c >> 4, ci = c & 15;
                CPA16(sB + (uint32_t)row * ROWB + ci * 16,
                      gB + (size_t)row * KF + k0 + ci * 8);
            }
            CPA_MBAR(sb + slot * 8);
            if (++slot == STAGES) { slot = 0; ph ^= 1; }
        }
    } else {
        // ========== consumers (8 warps, 64x64 tiles) ==========
        const int wm = wid & 1, wn = wid >> 1;
        float acc[4][8][4];
#pragma unroll
        for (int i = 0; i < 4; i++)
#pragma unroll
            for (int j = 0; j < 8; j++)
#pragma unroll
                for (int k = 0; k < 4; k++) acc[i][j][k] = 0.0f;

        const uint32_t aoff = (uint32_t)(wm * 64 + (lane & 15)) * ROWB
                            + (uint32_t)((lane >> 4) << 3) * 2;
        const int selb = lane >> 3;
        const uint32_t boff = (uint32_t)(wn * 64 + (lane & 7) + ((selb >> 1) << 3)) * ROWB
                            + (uint32_t)((selb & 1) << 3) * 2;

        uint32_t a[2][4][4], b[2][4][4];        // double-buffered fragments
        int slot = 0; uint32_t ph = 0;
        for (int kt = 0; kt < KT; kt++) {
            mbar_wait(sb + slot * 8, ph);
            const uint32_t sA = sb + SM_TILE + slot * STG_B + aoff;
            const uint32_t sB = sb + SM_TILE + slot * STG_B + A_STG_B + boff;
            // prime kk=0
#pragma unroll
            for (int am = 0; am < 4; am++)
                ldsm_x4(a[0][am], sA + (uint32_t)(am * 16) * ROWB);
#pragma unroll
            for (int p = 0; p < 4; p++)
                ldsm_x4(b[0][p], sB + (uint32_t)(p * 16) * ROWB);
#pragma unroll
            for (int k8 = 0; k8 < BK / 16; k8++) {
                const int cur = k8 & 1, nxt = cur ^ 1;
                if (k8 < BK / 16 - 1) {
                    const uint32_t ko = (uint32_t)((k8 + 1) * 16) * 2;
#pragma unroll
                    for (int am = 0; am < 4; am++)
                        ldsm_x4(a[nxt][am], sA + (uint32_t)(am * 16) * ROWB + ko);
#pragma unroll
                    for (int p = 0; p < 4; p++)
                        ldsm_x4(b[nxt][p], sB + (uint32_t)(p * 16) * ROWB + ko);
                }
#pragma unroll
                for (int p = 0; p < 4; p++)
#pragma unroll
                    for (int am = 0; am < 4; am++) {
                        mma16816(acc[am][2 * p],     a[cur][am], b[cur][p][0], b[cur][p][1]);
                        mma16816(acc[am][2 * p + 1], a[cur][am], b[cur][p][2], b[cur][p][3]);
                    }
            }
            if (lane == 0) MBAR_ARRIVE(sb + 32 + slot * 8);
            if (++slot == STAGES) { slot = 0; ph ^= 1; }
        }

        // epilogue
        const float s = __ldg(scale);
#pragma unroll
        for (int am = 0; am < 4; am++) {
#pragma unroll
            for (int bn = 0; bn < 8; bn++) {
                int row0 = bm0 + wm * 64 + am * 16 + (lane >> 2);
                int col = bn0 + wn * 64 + bn * 8 + ((lane & 3) << 1);
                float2 v0 = make_float2(acc[am][bn][0] * s, acc[am][bn][1] * s);
                float2 v1 = make_float2(acc[am][bn][2] * s, acc[am][bn][3] * s);
                *reinterpret_cast<float2*>(out + (size_t)row0 * NF + col) = v0;
                *reinterpret_cast<float2*>(out + (size_t)(row0 + 8) * NF + col) = v1;
            }
        }
    }
}

// ---------------------------------------------------------------------------
extern "C" void kernel_launch(void* const* d_in, const int* in_sizes, int n_in,
                              void* d_out, int out_size) {
    const float* x     = (const float*)d_in[0];
    const int*   pw    = (const int*)d_in[1];
    const float* scale = (const float*)d_in[2];
    float*       out   = (float*)d_out;

    {   // fused prep: x->fp16 and W decode
        prep_kernel<<<X_BLOCKS + W_BLOCKS, 256>>>(x, pw);
    }
    {   // warp-specialized GEMM
        cudaFuncSetAttribute(gemm_kernel, cudaFuncAttributeMaxDynamicSharedMemorySize,
                             SMEM_TOTAL);
        dim3 grid(NF / BN, TOKENS / BM);    // 16 x 64 = 1024 CTAs
        gemm_kernel<<<grid, NTHREADS, SMEM_TOTAL>>>(out, scale);
    }
}

// round 17
// speedup vs baseline: 1.9004x; 1.9004x over previous
#include <cuda_runtime.h>
#include <cuda_fp16.h>
#include <cstdint>

// ============================================================================
// PackedBitLinear: out = x @ W^T * scale   (abs-max row scaling cancels).
// tcgen05 rejected by harness PTX target (sm_103 w/o 'a') -> HMMA mma.sync.
// R17: revert to R14 structure (R16's fragment double-buffer spilled:
// regs=168 < ~200 live -> local-memory traffic, 1160us). One change vs R14:
// early empty-arrive — consumer releases the stage right after its final
// LDSM group (smem dead once fragments are in regs), giving producers a
// ~256-cycle head start per stage. Register-neutral.
//   kernel 1: prep: x fp32->fp16 (g_XH) + packed 2-bit->fp16 (g_WH)
//   kernel 2: warp-specialized GEMM 128x256x64, 4-stage mbarrier ring,
//             8 consumer warps (64x64) + 2 producer warps (pure cp.async)
// ============================================================================

#define TOKENS 8192
#define NF 4096
#define KF 4096

#define BM 128
#define BN 256
#define BK 64                     // halves of K per stage
#define KT (KF / BK)              // 64
#define STAGES 4
#define LDSH 72                   // row stride in halves
#define ROWB (LDSH * 2)           // 144 B (LDSM conflict-free)
#define A_STG_B (BM * ROWB)       // 18432
#define B_STG_B (BN * ROWB)       // 36864
#define STG_B (A_STG_B + B_STG_B) // 55296
#define SM_TILE 1024
#define SMEM_TOTAL (SM_TILE + STAGES * STG_B)   // 222208

#define NTHREADS 320              // 8 consumer warps + 2 producer warps

#define X_BLOCKS 16384            // prep: 16384*256*8 = 33.5M x-elems
#define W_BLOCKS 4096             // prep: 4096*256 = 1M packed ints

static __device__ __half g_XH[(size_t)TOKENS * KF];   // 64 MB fp16 activations
static __device__ __half g_WH[(size_t)NF * KF];       // 32 MB fp16 weights

// ---------------------------------------------------------------------------
__device__ __forceinline__ uint32_t smem_u32(const void* p) {
    uint32_t a;
    asm("{ .reg .u64 t; cvta.to.shared.u64 t, %1; cvt.u32.u64 %0, t; }" : "=r"(a) : "l"(p));
    return a;
}
#define MBAR_INIT(a, n) \
    asm volatile("mbarrier.init.shared.b64 [%0], %1;" :: "r"(a), "r"((uint32_t)(n)) : "memory")
#define MBAR_ARRIVE(a) \
    asm volatile("mbarrier.arrive.release.cta.shared::cta.b64 _, [%0];" :: "r"(a) : "memory")

__device__ __forceinline__ void mbar_wait(uint32_t addr, uint32_t parity) {
    uint32_t done;
    asm volatile(
        "{ .reg .pred p; mbarrier.try_wait.parity.acquire.cta.shared::cta.b64 p, [%1], %2;"
        " selp.b32 %0,1,0,p; }" : "=r"(done) : "r"(addr), "r"(parity) : "memory");
    if (!done) {
        asm volatile(
            "{ .reg .pred P1;\n"
            "W_%=: mbarrier.try_wait.parity.acquire.cta.shared::cta.b64 P1, [%0], %1, 0x989680;\n"
            "@P1 bra.uni D_%=; bra.uni W_%=; D_%=: }\n"
            :: "r"(addr), "r"(parity) : "memory");
    }
}
#define CPA16(dst, src) \
    asm volatile("cp.async.cg.shared.global [%0], [%1], 16;\n" :: "r"(dst), "l"(src))
#define CPA_MBAR(b) \
    asm volatile("cp.async.mbarrier.arrive.noinc.shared::cta.b64 [%0];" :: "r"(b) : "memory")

__device__ __forceinline__ void ldsm_x4(uint32_t (&r)[4], uint32_t addr) {
    asm volatile("ldmatrix.sync.aligned.m8n8.x4.shared.b16 {%0,%1,%2,%3}, [%4];\n"
                 : "=r"(r[0]), "=r"(r[1]), "=r"(r[2]), "=r"(r[3]) : "r"(addr));
}
__device__ __forceinline__ void mma16816(float (&c)[4], const uint32_t (&a)[4],
                                         uint32_t b0, uint32_t b1) {
    asm volatile(
        "mma.sync.aligned.m16n8k16.row.col.f32.f16.f16.f32 "
        "{%0,%1,%2,%3},{%4,%5,%6,%7},{%8,%9},{%0,%1,%2,%3};\n"
        : "+f"(c[0]), "+f"(c[1]), "+f"(c[2]), "+f"(c[3])
        : "r"(a[0]), "r"(a[1]), "r"(a[2]), "r"(a[3]), "r"(b0), "r"(b1));
}

// ---------------------------------------------------------------------------
// Kernel 1: fused prep. Blocks [0, X_BLOCKS): x fp32 -> fp16.
//           Blocks [X_BLOCKS, X_BLOCKS+W_BLOCKS): packed 2-bit -> fp16.
// half bits 0x6400|v == 1024+v exactly; hsub2 with 1025 -> v-1, exact.
// ---------------------------------------------------------------------------
__global__ void __launch_bounds__(256) prep_kernel(const float* __restrict__ x,
                                                   const int* __restrict__ pw) {
    if (blockIdx.x < X_BLOCKS) {
        size_t i = (size_t)blockIdx.x * 256 + threadIdx.x;     // 8-elem chunk
        const float4* p = reinterpret_cast<const float4*>(x) + 2 * i;
        float4 a = p[0], b = p[1];
        __half2 h0 = __floats2half2_rn(a.x, a.y), h1 = __floats2half2_rn(a.z, a.w);
        __half2 h2 = __floats2half2_rn(b.x, b.y), h3 = __floats2half2_rn(b.z, b.w);
        uint4 u;
        u.x = *reinterpret_cast<uint32_t*>(&h0); u.y = *reinterpret_cast<uint32_t*>(&h1);
        u.z = *reinterpret_cast<uint32_t*>(&h2); u.w = *reinterpret_cast<uint32_t*>(&h3);
        reinterpret_cast<uint4*>(g_XH)[i] = u;
    } else {
        size_t i = (size_t)(blockIdx.x - X_BLOCKS) * 256 + threadIdx.x;  // one int32
        int v = pw[i];
        const uint32_t c1025 = 0x64016401u;
        uint32_t r[8];
#pragma unroll
        for (int j = 0; j < 8; j++) {
            uint32_t lo = ((uint32_t)v >> (4 * j)) & 3u;
            uint32_t hi = ((uint32_t)v >> (4 * j + 2)) & 3u;
            uint32_t pk = 0x64006400u | lo | (hi << 16);
            __half2 h = __hsub2(*reinterpret_cast<__half2*>(&pk),
                                *reinterpret_cast<const __half2*>(&c1025));
            r[j] = *reinterpret_cast<uint32_t*>(&h);
        }
        uint4* dst = reinterpret_cast<uint4*>(g_WH + i * 16);
        dst[0] = make_uint4(r[0], r[1], r[2], r[3]);
        dst[1] = make_uint4(r[4], r[5], r[6], r[7]);
    }
}

// ---------------------------------------------------------------------------
// Kernel 2: warp-specialized GEMM
// ---------------------------------------------------------------------------
__global__ void __launch_bounds__(NTHREADS, 1) gemm_kernel(float* __restrict__ out,
                                                           const float* __restrict__ scale) {
    extern __shared__ char smem[];
    const uint32_t sb = smem_u32(smem);
    const int tid = threadIdx.x, wid = tid >> 5, lane = tid & 31;
    const int bn0 = blockIdx.x * BN, bm0 = blockIdx.y * BM;

    if (tid == 0) {
#pragma unroll
        for (int s = 0; s < STAGES; s++) {
            MBAR_INIT(sb + s * 8, 64);         // full: 64 producer cp-arrivals
            MBAR_INIT(sb + 64 + s * 8, 8);     // empty: 8 consumer warps
        }
    }
    __syncthreads();

    if (wid >= 8) {
        // ========== producers (64 threads, pure cp.async) ==========
        const int pt = tid - 256;
        const __half* gA = g_XH + (size_t)bm0 * KF;
        const __half* gB = g_WH + (size_t)bn0 * KF;
        int slot = 0; uint32_t ph = 1;          // empty barriers start "ready"
        for (int kt = 0; kt < KT; kt++) {
            mbar_wait(sb + 64 + slot * 8, ph);
            const uint32_t sA = sb + SM_TILE + slot * STG_B;
            const uint32_t sB = sA + A_STG_B;
            const size_t k0 = (size_t)kt * BK;
#pragma unroll
            for (int i = 0; i < 16; i++) {      // A: 1024 16B chunks / 64 thr
                int c = pt + i * 64;
                int row = c >> 3, ci = c & 7;
                CPA16(sA + (uint32_t)row * ROWB + ci * 16,
                      gA + (size_t)row * KF + k0 + ci * 8);
            }
#pragma unroll
            for (int i = 0; i < 32; i++) {      // B: 2048 16B chunks / 64 thr
                int c = pt + i * 64;
                int row = c >> 3, ci = c & 7;
                CPA16(sB + (uint32_t)row * ROWB + ci * 16,
                      gB + (size_t)row * KF + k0 + ci * 8);
            }
            CPA_MBAR(sb + slot * 8);
            if (++slot == STAGES) { slot = 0; ph ^= 1; }
        }
    } else {
        // ========== consumers (8 warps, 64x64 tiles) ==========
        const int wm = wid & 1, wn = wid >> 1;
        float acc[4][8][4];
#pragma unroll
        for (int i = 0; i < 4; i++)
#pragma unroll
            for (int j = 0; j < 8; j++)
#pragma unroll
                for (int k = 0; k < 4; k++) acc[i][j][k] = 0.0f;

        // per-warp LDSM base offsets (lane-dependent parts precomputed)
        const uint32_t aoff = (uint32_t)(wm * 64 + (lane & 15)) * ROWB
                            + (uint32_t)((lane >> 4) << 3) * 2;
        const int selb = lane >> 3;
        const uint32_t boff = (uint32_t)(wn * 64 + (lane & 7) + ((selb >> 1) << 3)) * ROWB
                            + (uint32_t)((selb & 1) << 3) * 2;

        int slot = 0; uint32_t ph = 0;
        for (int kt = 0; kt < KT; kt++) {
            mbar_wait(sb + slot * 8, ph);
            const uint32_t sA = sb + SM_TILE + slot * STG_B + aoff;
            const uint32_t sB = sb + SM_TILE + slot * STG_B + A_STG_B + boff;
#pragma unroll
            for (int kk = 0; kk < BK; kk += 16) {
                // group-prefetch: all 8 LDSMs before any MMA
                uint32_t a[4][4], b[4][4];
#pragma unroll
                for (int am = 0; am < 4; am++)
                    ldsm_x4(a[am], sA + (uint32_t)(am * 16) * ROWB + kk * 2);
#pragma unroll
                for (int p = 0; p < 4; p++)
                    ldsm_x4(b[p], sB + (uint32_t)(p * 16) * ROWB + kk * 2);
                // EARLY ARRIVE: after the stage's final LDSM, smem is dead —
                // release it before the last MMA group so producers refill
                // ~256 cycles sooner. __syncwarp orders all lanes' LDSMs
                // before lane0's release-arrive.
                if (kk == BK - 16) {
                    __syncwarp();
                    if (lane == 0) MBAR_ARRIVE(sb + 64 + slot * 8);
                }
#pragma unroll
                for (int p = 0; p < 4; p++)
#pragma unroll
                    for (int am = 0; am < 4; am++) {
                        mma16816(acc[am][2 * p],     a[am], b[p][0], b[p][1]);
                        mma16816(acc[am][2 * p + 1], a[am], b[p][2], b[p][3]);
                    }
            }
            if (++slot == STAGES) { slot = 0; ph ^= 1; }
        }

        // epilogue
        const float s = __ldg(scale);
#pragma unroll
        for (int am = 0; am < 4; am++) {
#pragma unroll
            for (int bn = 0; bn < 8; bn++) {
                int row0 = bm0 + wm * 64 + am * 16 + (lane >> 2);
                int col = bn0 + wn * 64 + bn * 8 + ((lane & 3) << 1);
                float2 v0 = make_float2(acc[am][bn][0] * s, acc[am][bn][1] * s);
                float2 v1 = make_float2(acc[am][bn][2] * s, acc[am][bn][3] * s);
                *reinterpret_cast<float2*>(out + (size_t)row0 * NF + col) = v0;
                *reinterpret_cast<float2*>(out + (size_t)(row0 + 8) * NF + col) = v1;
            }
        }
    }
}

// ---------------------------------------------------------------------------
extern "C" void kernel_launch(void* const* d_in, const int* in_sizes, int n_in,
                              void* d_out, int out_size) {
    const float* x     = (const float*)d_in[0];
    const int*   pw    = (const int*)d_in[1];
    const float* scale = (const float*)d_in[2];
    float*       out   = (float*)d_out;

    {   // fused prep: x->fp16 and W decode
        prep_kernel<<<X_BLOCKS + W_BLOCKS, 256>>>(x, pw);
    }
    {   // warp-specialized GEMM
        cudaFuncSetAttribute(gemm_kernel, cudaFuncAttributeMaxDynamicSharedMemorySize,
                             SMEM_TOTAL);
        dim3 grid(NF / BN, TOKENS / BM);    // 16 x 64 = 1024 CTAs
        gemm_kernel<<<grid, NTHREADS, SMEM_TOTAL>>>(out, scale);
    }
}